// round 5
// baseline (speedup 1.0000x reference)
#include <cuda_runtime.h>
#include <math.h>
#include <cstdint>

#define TT 2048      // tokens = B*S
#define EE 8         // experts
#define HH 768       // hidden
#define FF 3072      // ffn hidden

// ---------------- scratch (__device__ globals: allocation-free rule) --------
__device__ float g_hmid[(size_t)TT * 2 * FF];   // 50 MB (tf32-rounded)
__device__ float g_xc [(size_t)TT * HH];        // 6 MB  (tf32-rounded x)
__device__ float g_w1c[(size_t)EE * FF * HH];   // 75 MB (tf32-rounded w1)
__device__ float g_w2c[(size_t)EE * HH * FF];   // 75 MB (tf32-rounded w2)
__device__ int   g_cnt[EE];
__device__ int   g_list[EE * TT];
__device__ float g_slot_w[TT * 2];

// ---------------- helpers ----------------------------------------------------
__device__ __forceinline__ uint32_t smem_u32(const void* p) {
    uint32_t a;
    asm("{ .reg .u64 t; cvta.to.shared.u64 t, %1; cvt.u32.u64 %0, t; }" : "=r"(a) : "l"(p));
    return a;
}
__device__ __forceinline__ void cpa16(uint32_t dst, const void* src) {
    asm volatile("cp.async.cg.shared.global [%0], [%1], 16;\n" :: "r"(dst), "l"(src));
}
__device__ __forceinline__ void cpa_commit() { asm volatile("cp.async.commit_group;\n" ::: "memory"); }
__device__ __forceinline__ void cpa_wait2()  { asm volatile("cp.async.wait_group 2;\n" ::: "memory"); }

__device__ __forceinline__ void ldsm4(uint32_t r[4], uint32_t addr) {
    asm volatile("ldmatrix.sync.aligned.m8n8.x4.shared.b16 {%0,%1,%2,%3}, [%4];"
                 : "=r"(r[0]), "=r"(r[1]), "=r"(r[2]), "=r"(r[3]) : "r"(addr));
}
__device__ __forceinline__ float tf32r(float v) {
    uint32_t t;
    asm("cvt.rna.tf32.f32 %0, %1;" : "=r"(t) : "f"(v));
    return __uint_as_float(t);
}
__device__ __forceinline__ void mma8(float c[4], const uint32_t a[4],
                                     uint32_t b0, uint32_t b1) {
    asm volatile(
        "mma.sync.aligned.m16n8k8.row.col.f32.tf32.tf32.f32 "
        "{%0,%1,%2,%3}, {%4,%5,%6,%7}, {%8,%9}, {%0,%1,%2,%3};"
        : "+f"(c[0]), "+f"(c[1]), "+f"(c[2]), "+f"(c[3])
        : "r"(a[0]), "r"(a[1]), "r"(a[2]), "r"(a[3]), "r"(b0), "r"(b1));
}

// ---------------- init / router / convert ------------------------------------
__global__ void init_kernel(float* out, int out_size) {
    int i = blockIdx.x * blockDim.x + threadIdx.x;
    if (i < out_size) out[i] = 0.0f;
    if (i < EE) g_cnt[i] = 0;
}

__global__ void cvt_kernel(const float4* __restrict__ src, float4* __restrict__ dst, int n4) {
    int i = blockIdx.x * blockDim.x + threadIdx.x;
    int stride = gridDim.x * blockDim.x;
    for (; i < n4; i += stride) {
        float4 v = src[i];
        v.x = tf32r(v.x); v.y = tf32r(v.y); v.z = tf32r(v.z); v.w = tf32r(v.w);
        dst[i] = v;
    }
}

// Router also writes the tf32-rounded copy of x (g_xc).
__global__ void router_kernel(const float* __restrict__ x,
                              const float* __restrict__ rw) {
    int gw   = (blockIdx.x * blockDim.x + threadIdx.x) >> 5;
    int lane = threadIdx.x & 31;
    if (gw >= TT) return;
    const float* xt = x + (size_t)gw * HH;
    float xv[HH / 32];
#pragma unroll
    for (int i = 0; i < HH / 32; i++) xv[i] = xt[lane + 32 * i];
    float* xc = g_xc + (size_t)gw * HH;
#pragma unroll
    for (int i = 0; i < HH / 32; i++) xc[lane + 32 * i] = tf32r(xv[i]);
    float lg[EE];
#pragma unroll
    for (int e = 0; e < EE; e++) {
        const float* w = rw + (size_t)e * HH;
        float s = 0.0f;
#pragma unroll
        for (int i = 0; i < HH / 32; i++) s = fmaf(xv[i], w[lane + 32 * i], s);
#pragma unroll
        for (int o = 16; o; o >>= 1) s += __shfl_xor_sync(0xffffffffu, s, o);
        lg[e] = s;
    }
    if (lane == 0) {
        int i0 = 0;
#pragma unroll
        for (int e = 1; e < EE; e++) if (lg[e] > lg[i0]) i0 = e;
        int i1 = (i0 == 0) ? 1 : 0;
#pragma unroll
        for (int e = 0; e < EE; e++) {
            if (e == i0 || e == i1) continue;
            if (lg[e] > lg[i1]) i1 = e;
        }
        float ex = expf(lg[i1] - lg[i0]);
        float inv = 1.0f / (1.0f + ex);
        g_slot_w[gw * 2]     = inv;
        g_slot_w[gw * 2 + 1] = ex * inv;
        int p = atomicAdd(&g_cnt[i0], 1); g_list[i0 * TT + p] = gw * 2;
        int q = atomicAdd(&g_cnt[i1], 1); g_list[i1 * TT + q] = gw * 2 + 1;
    }
}

// ---------------- mma.sync tf32 grouped GEMM, reg-pipelined ------------------
// MODE 0: A = g_xc[token],  W = g_w1c[e] -> bias + GELU -> tf32 -> g_hmid[slot]
// MODE 1: A = g_hmid[slot], W = g_w2c[e] -> weighted atomicAdd into Out (split-K)
template <int MODE, int KD, int ND, int NSPLIT>
__global__ __launch_bounds__(256, 1) void moe_gemm(
    const float* __restrict__ W,
    const float* __restrict__ bias, float* __restrict__ Out) {
    constexpr int BM = 128, BN = 128, BK = 32, STAGES = 4;
    constexpr int KSP = KD / NSPLIT;
    constexpr int NSLAB = KSP / BK;
    constexpr int STAGE = (BM + BN) * BK * 4;   // 32 KB

    extern __shared__ char dsm[];
    __shared__ int s_slot[BM];

    int e = blockIdx.z / NSPLIT, split = blockIdx.z % NSPLIT;
    int cnt = g_cnt[e];
    int m0 = blockIdx.y * BM;
    if (m0 >= cnt) return;
    int n0 = blockIdx.x * BN;
    int kbase = split * KSP;
    int tid = threadIdx.x, lane = tid & 31, wid = tid >> 5;
    int wm = (wid & 3) * 32, wn = (wid >> 2) * 64;

    const float* __restrict__ Ap = (MODE == 0) ? g_xc : g_hmid;
    const float* __restrict__ Wb = W + (size_t)e * ND * KD;

    for (int i = tid; i < BM; i += 256) {
        int r = m0 + i;
        s_slot[i] = g_list[e * TT + (r < cnt ? r : cnt - 1)];
    }
    __syncthreads();

    uint32_t sb = (smem_u32(dsm) + 127u) & ~127u;

    auto fill = [&](int st, int s) {
        int k0 = kbase + s * BK;
        uint32_t as = sb + st * STAGE;
        uint32_t bs = as + BM * 128;
#pragma unroll
        for (int j = 0; j < 4; j++) {
            int idx = tid + j * 256;
            int r = idx >> 3, c = idx & 7;
            size_t arow = (MODE == 0) ? (size_t)(s_slot[r] >> 1) : (size_t)s_slot[r];
            cpa16(as + r * 128 + ((c * 16) ^ ((r & 7) << 4)),
                  Ap + arow * KD + k0 + c * 4);
        }
#pragma unroll
        for (int j = 0; j < 4; j++) {
            int idx = tid + j * 256;
            int r = idx >> 3, c = idx & 7;
            cpa16(bs + r * 128 + ((c * 16) ^ ((r & 7) << 4)),
                  Wb + (size_t)(n0 + r) * KD + k0 + c * 4);
        }
    };

    fill(0, 0); cpa_commit();
    fill(1, 1); cpa_commit();
    fill(2, 2); cpa_commit();

    float acc[2][8][4];
#pragma unroll
    for (int mt = 0; mt < 2; mt++)
#pragma unroll
        for (int nt = 0; nt < 8; nt++)
#pragma unroll
            for (int q = 0; q < 4; q++) acc[mt][nt][q] = 0.0f;

    int a_row = lane & 15;
    int a_kx  = (lane >> 4) << 4;
    int b_row = lane & 7;
    int b_kx  = (lane >> 3) << 4;

    uint32_t Bf[2][8][4];      // double-buffered B fragments (per k-half)
    uint32_t Af[2][2][4];      // double-buffered A fragments (per k8 step)

    for (int s = 0; s < NSLAB; s++) {
        cpa_wait2();
        __syncthreads();

        uint32_t ab = sb + (s & 3) * STAGE;
        uint32_t bb = ab + BM * 128;

        // start the first ldsm chains of this slab ASAP
#pragma unroll
        for (int nt = 0; nt < 8; nt++) {                 // B, k-half 0
            int row = wn + nt * 8 + b_row;
            ldsm4(Bf[0][nt], bb + row * 128 + ((0 + b_kx) ^ ((row & 7) << 4)));
        }
#pragma unroll
        for (int mt = 0; mt < 2; mt++) {                 // A, kh0 ks0
            int row = wm + mt * 16 + a_row;
            ldsm4(Af[0][mt], ab + row * 128 + ((0 + a_kx) ^ ((row & 7) << 4)));
        }

        // overlap next-stage global prefetch with fragment latency
        if (s + 3 < NSLAB) fill((s + 3) & 3, s + 3);
        cpa_commit();

#pragma unroll
        for (int mt = 0; mt < 2; mt++) {                 // A, kh0 ks1
            int row = wm + mt * 16 + a_row;
            ldsm4(Af[1][mt], ab + row * 128 + ((32 + a_kx) ^ ((row & 7) << 4)));
        }
#pragma unroll
        for (int nt = 0; nt < 8; nt++) {                 // B, k-half 1
            int row = wn + nt * 8 + b_row;
            ldsm4(Bf[1][nt], bb + row * 128 + ((64 + b_kx) ^ ((row & 7) << 4)));
        }

        // kh0 ks0
#pragma unroll
        for (int mt = 0; mt < 2; mt++)
#pragma unroll
            for (int nt = 0; nt < 8; nt++)
                mma8(acc[mt][nt], Af[0][mt], Bf[0][nt][0], Bf[0][nt][1]);

#pragma unroll
        for (int mt = 0; mt < 2; mt++) {                 // A, kh1 ks0
            int row = wm + mt * 16 + a_row;
            ldsm4(Af[0][mt], ab + row * 128 + ((64 + a_kx) ^ ((row & 7) << 4)));
        }
        // kh0 ks1
#pragma unroll
        for (int mt = 0; mt < 2; mt++)
#pragma unroll
            for (int nt = 0; nt < 8; nt++)
                mma8(acc[mt][nt], Af[1][mt], Bf[0][nt][2], Bf[0][nt][3]);

#pragma unroll
        for (int mt = 0; mt < 2; mt++) {                 // A, kh1 ks1
            int row = wm + mt * 16 + a_row;
            ldsm4(Af[1][mt], ab + row * 128 + ((96 + a_kx) ^ ((row & 7) << 4)));
        }
        // kh1 ks0
#pragma unroll
        for (int mt = 0; mt < 2; mt++)
#pragma unroll
            for (int nt = 0; nt < 8; nt++)
                mma8(acc[mt][nt], Af[0][mt], Bf[1][nt][0], Bf[1][nt][1]);
        // kh1 ks1
#pragma unroll
        for (int mt = 0; mt < 2; mt++)
#pragma unroll
            for (int nt = 0; nt < 8; nt++)
                mma8(acc[mt][nt], Af[1][mt], Bf[1][nt][2], Bf[1][nt][3]);
    }

    // ---------------- epilogue ----------------
    int g = lane >> 2, tig = lane & 3;
#pragma unroll
    for (int mt = 0; mt < 2; mt++) {
#pragma unroll
        for (int half = 0; half < 2; half++) {
            int rl = wm + mt * 16 + g + half * 8;
            if (m0 + rl >= cnt) continue;
            int slot = s_slot[rl];
            if (MODE == 0) {
                float* dst = g_hmid + (size_t)slot * ND;
                const float* bp = bias + (size_t)e * ND;
#pragma unroll
                for (int nt = 0; nt < 8; nt++) {
                    int col = n0 + wn + nt * 8 + 2 * tig;
                    float v0 = acc[mt][nt][half * 2 + 0] + bp[col];
                    float v1 = acc[mt][nt][half * 2 + 1] + bp[col + 1];
                    v0 = 0.5f * v0 * (1.0f + erff(v0 * 0.70710678118654752f));
                    v1 = 0.5f * v1 * (1.0f + erff(v1 * 0.70710678118654752f));
                    *(float2*)(dst + col) = make_float2(tf32r(v0), tf32r(v1));
                }
            } else {
                float wgt = g_slot_w[slot];
                float* dst = Out + (size_t)(slot >> 1) * ND;
                const float* bp = bias + (size_t)e * ND;
#pragma unroll
                for (int nt = 0; nt < 8; nt++) {
                    int col = n0 + wn + nt * 8 + 2 * tig;
                    float v0 = acc[mt][nt][half * 2 + 0] + (split == 0 ? bp[col] : 0.0f);
                    float v1 = acc[mt][nt][half * 2 + 1] + (split == 0 ? bp[col + 1] : 0.0f);
                    atomicAdd(dst + col,     wgt * v0);
                    atomicAdd(dst + col + 1, wgt * v1);
                }
            }
        }
    }
}

// ---------------- launcher ---------------------------------------------------
extern "C" void kernel_launch(void* const* d_in, const int* in_sizes, int n_in,
                              void* d_out, int out_size) {
    const float* x  = (const float*)d_in[0];
    const float* rw = (const float*)d_in[1];
    const float* w1 = (const float*)d_in[2];
    const float* b1 = (const float*)d_in[3];
    const float* w2 = (const float*)d_in[4];
    const float* b2 = (const float*)d_in[5];
    float* out = (float*)d_out;

    void *p_w1c, *p_w2c;
    cudaGetSymbolAddress(&p_w1c, g_w1c);
    cudaGetSymbolAddress(&p_w2c, g_w2c);

    const int SMEM = 4 * 32768 + 128;
    cudaFuncSetAttribute(moe_gemm<0, HH, FF, 1>,
                         cudaFuncAttributeMaxDynamicSharedMemorySize, SMEM);
    cudaFuncSetAttribute(moe_gemm<1, FF, HH, 2>,
                         cudaFuncAttributeMaxDynamicSharedMemorySize, SMEM);

    init_kernel<<<(out_size + 255) / 256, 256>>>(out, out_size);
    router_kernel<<<(TT * 32) / 256, 256>>>(x, rw);

    cvt_kernel<<<4736, 256>>>((const float4*)w1, (float4*)p_w1c, EE * FF * HH / 4);
    cvt_kernel<<<4736, 256>>>((const float4*)w2, (float4*)p_w2c, EE * HH * FF / 4);

    // GEMM1: slots x w1^T -> GELU -> hmid (tf32-rounded)
    dim3 g1(FF / 128, (TT + 127) / 128, EE);
    moe_gemm<0, HH, FF, 1><<<g1, 256, SMEM>>>((const float*)p_w1c, b1, out);

    // GEMM2: hmid x w2^T -> weighted scatter-add into out (split-K = 2)
    dim3 g2(HH / 128, (TT + 127) / 128, EE * 2);
    moe_gemm<1, FF, HH, 2><<<g2, 256, SMEM>>>((const float*)p_w2c, b2, out);
}

// round 6
// speedup vs baseline: 1.0075x; 1.0075x over previous
#include <cuda_runtime.h>
#include <math.h>
#include <cstdint>

#define TT 2048      // tokens = B*S
#define EE 8         // experts
#define HH 768       // hidden
#define FF 3072      // ffn hidden

// ---------------- scratch (__device__ globals: allocation-free rule) --------
__device__ float g_hmid[(size_t)TT * 2 * FF];   // 50 MB (tf32-rounded)
__device__ float g_xc [(size_t)TT * HH];        // 6 MB  (tf32-rounded x)
__device__ float g_w1c[(size_t)EE * FF * HH];   // 75 MB (tf32-rounded w1)
__device__ float g_w2c[(size_t)EE * HH * FF];   // 75 MB (tf32-rounded w2)
__device__ int   g_cnt[EE];
__device__ int   g_list[EE * TT];
__device__ float g_slot_w[TT * 2];

// ---------------- helpers ----------------------------------------------------
__device__ __forceinline__ uint32_t smem_u32(const void* p) {
    uint32_t a;
    asm("{ .reg .u64 t; cvta.to.shared.u64 t, %1; cvt.u32.u64 %0, t; }" : "=r"(a) : "l"(p));
    return a;
}
__device__ __forceinline__ void cpa16(uint32_t dst, const void* src) {
    asm volatile("cp.async.cg.shared.global [%0], [%1], 16;\n" :: "r"(dst), "l"(src));
}
__device__ __forceinline__ void cpa_commit() { asm volatile("cp.async.commit_group;\n" ::: "memory"); }
__device__ __forceinline__ void cpa_wait2()  { asm volatile("cp.async.wait_group 2;\n" ::: "memory"); }

__device__ __forceinline__ void ldsm4(uint32_t r[4], uint32_t addr) {
    asm volatile("ldmatrix.sync.aligned.m8n8.x4.shared.b16 {%0,%1,%2,%3}, [%4];"
                 : "=r"(r[0]), "=r"(r[1]), "=r"(r[2]), "=r"(r[3]) : "r"(addr));
}
__device__ __forceinline__ float tf32r(float v) {
    uint32_t t;
    asm("cvt.rna.tf32.f32 %0, %1;" : "=r"(t) : "f"(v));
    return __uint_as_float(t);
}
__device__ __forceinline__ void mma8(float c[4], const uint32_t a[4],
                                     uint32_t b0, uint32_t b1) {
    asm volatile(
        "mma.sync.aligned.m16n8k8.row.col.f32.tf32.tf32.f32 "
        "{%0,%1,%2,%3}, {%4,%5,%6,%7}, {%8,%9}, {%0,%1,%2,%3};"
        : "+f"(c[0]), "+f"(c[1]), "+f"(c[2]), "+f"(c[3])
        : "r"(a[0]), "r"(a[1]), "r"(a[2]), "r"(a[3]), "r"(b0), "r"(b1));
}

// ---------------- init / router / convert ------------------------------------
__global__ void init_kernel(float* out, int out_size) {
    int i = blockIdx.x * blockDim.x + threadIdx.x;
    if (i < out_size) out[i] = 0.0f;
    if (i < EE) g_cnt[i] = 0;
}

__global__ void cvt_kernel(const float4* __restrict__ src, float4* __restrict__ dst, int n4) {
    int i = blockIdx.x * blockDim.x + threadIdx.x;
    int stride = gridDim.x * blockDim.x;
    for (; i < n4; i += stride) {
        float4 v = src[i];
        v.x = tf32r(v.x); v.y = tf32r(v.y); v.z = tf32r(v.z); v.w = tf32r(v.w);
        dst[i] = v;
    }
}

// Router also writes the tf32-rounded copy of x (g_xc).
__global__ void router_kernel(const float* __restrict__ x,
                              const float* __restrict__ rw) {
    int gw   = (blockIdx.x * blockDim.x + threadIdx.x) >> 5;
    int lane = threadIdx.x & 31;
    if (gw >= TT) return;
    const float* xt = x + (size_t)gw * HH;
    float xv[HH / 32];
#pragma unroll
    for (int i = 0; i < HH / 32; i++) xv[i] = xt[lane + 32 * i];
    float* xc = g_xc + (size_t)gw * HH;
#pragma unroll
    for (int i = 0; i < HH / 32; i++) xc[lane + 32 * i] = tf32r(xv[i]);
    float lg[EE];
#pragma unroll
    for (int e = 0; e < EE; e++) {
        const float* w = rw + (size_t)e * HH;
        float s = 0.0f;
#pragma unroll
        for (int i = 0; i < HH / 32; i++) s = fmaf(xv[i], w[lane + 32 * i], s);
#pragma unroll
        for (int o = 16; o; o >>= 1) s += __shfl_xor_sync(0xffffffffu, s, o);
        lg[e] = s;
    }
    if (lane == 0) {
        int i0 = 0;
#pragma unroll
        for (int e = 1; e < EE; e++) if (lg[e] > lg[i0]) i0 = e;
        int i1 = (i0 == 0) ? 1 : 0;
#pragma unroll
        for (int e = 0; e < EE; e++) {
            if (e == i0 || e == i1) continue;
            if (lg[e] > lg[i1]) i1 = e;
        }
        float ex = expf(lg[i1] - lg[i0]);
        float inv = 1.0f / (1.0f + ex);
        g_slot_w[gw * 2]     = inv;
        g_slot_w[gw * 2 + 1] = ex * inv;
        int p = atomicAdd(&g_cnt[i0], 1); g_list[i0 * TT + p] = gw * 2;
        int q = atomicAdd(&g_cnt[i1], 1); g_list[i1 * TT + q] = gw * 2 + 1;
    }
}

// ---------------- mma.sync tf32 grouped GEMM, 64x64 warp tile ----------------
// CTA tile 128x256, 8 warps (2m x 4n), 4-stage cp.async.
// MODE 0: A = g_xc[token],  W = g_w1c[e] -> bias + GELU -> tf32 -> g_hmid[slot]
// MODE 1: A = g_hmid[slot], W = g_w2c[e] -> weighted atomicAdd into Out (split-K)
template <int MODE, int KD, int ND, int NSPLIT>
__global__ __launch_bounds__(256, 1) void moe_gemm(
    const float* __restrict__ W,
    const float* __restrict__ bias, float* __restrict__ Out) {
    constexpr int BM = 128, BN = 256, BK = 32;
    constexpr int KSP = KD / NSPLIT;
    constexpr int NSLAB = KSP / BK;
    constexpr int STAGE = (BM + BN) * BK * 4;   // 48 KB
    constexpr int ABYTES = BM * 128;            // 16 KB

    extern __shared__ char dsm[];
    __shared__ int s_slot[BM];

    int e = blockIdx.z / NSPLIT, split = blockIdx.z % NSPLIT;
    int cnt = g_cnt[e];
    int m0 = blockIdx.y * BM;
    if (m0 >= cnt) return;
    int n0 = blockIdx.x * BN;
    int kbase = split * KSP;
    int tid = threadIdx.x, lane = tid & 31, wid = tid >> 5;
    int wm = (wid & 1) * 64, wn = (wid >> 1) * 64;   // 2m x 4n warps, 64x64 tile

    const float* __restrict__ Ap = (MODE == 0) ? g_xc : g_hmid;
    const float* __restrict__ Wb = W + (size_t)e * ND * KD;

    for (int i = tid; i < BM; i += 256) {
        int r = m0 + i;
        s_slot[i] = g_list[e * TT + (r < cnt ? r : cnt - 1)];
    }
    __syncthreads();

    uint32_t sb = (smem_u32(dsm) + 127u) & ~127u;

    auto fill = [&](int st, int s) {
        int k0 = kbase + s * BK;
        uint32_t as = sb + st * STAGE;
        uint32_t bs = as + ABYTES;
#pragma unroll
        for (int j = 0; j < 4; j++) {                  // A: 128 rows x 128B
            int idx = tid + j * 256;
            int r = idx >> 3, c = idx & 7;
            size_t arow = (MODE == 0) ? (size_t)(s_slot[r] >> 1) : (size_t)s_slot[r];
            cpa16(as + r * 128 + ((c * 16) ^ ((r & 7) << 4)),
                  Ap + arow * KD + k0 + c * 4);
        }
#pragma unroll
        for (int j = 0; j < 8; j++) {                  // B: 256 rows x 128B
            int idx = tid + j * 256;
            int r = idx >> 3, c = idx & 7;
            cpa16(bs + r * 128 + ((c * 16) ^ ((r & 7) << 4)),
                  Wb + (size_t)(n0 + r) * KD + k0 + c * 4);
        }
    };

    fill(0, 0); cpa_commit();
    fill(1, 1); cpa_commit();
    fill(2, 2); cpa_commit();

    float acc[4][8][4];
#pragma unroll
    for (int mt = 0; mt < 4; mt++)
#pragma unroll
        for (int nt = 0; nt < 8; nt++)
#pragma unroll
            for (int q = 0; q < 4; q++) acc[mt][nt][q] = 0.0f;

    int a_row = lane & 15;            // row within m16 tile
    int a_kx  = (lane >> 4) << 4;     // 0 or 16 bytes
    int b_row = lane & 7;             // row within n8 tile
    int b_kx  = (lane >> 3) << 4;     // 0,16,32,48 bytes

    for (int s = 0; s < NSLAB; s++) {
        cpa_wait2();
        __syncthreads();
        uint32_t ab = sb + (s & 3) * STAGE;
        uint32_t bb = ab + ABYTES;

        if (s + 3 < NSLAB) fill((s + 3) & 3, s + 3);
        cpa_commit();

#pragma unroll
        for (int kh = 0; kh < 2; kh++) {          // 64-byte k-halves of the slab
            uint32_t b[8][4];
#pragma unroll
            for (int nt = 0; nt < 8; nt++) {
                int row = wn + nt * 8 + b_row;
                int kb  = kh * 64 + b_kx;
                ldsm4(b[nt], bb + row * 128 + (kb ^ ((row & 7) << 4)));
            }
            uint32_t a[2][4][4];                  // [ks][mt][frag]
#pragma unroll
            for (int ks = 0; ks < 2; ks++)
#pragma unroll
                for (int mt = 0; mt < 4; mt++) {
                    int row = wm + mt * 16 + a_row;
                    int kb  = kh * 64 + ks * 32 + a_kx;
                    ldsm4(a[ks][mt], ab + row * 128 + (kb ^ ((row & 7) << 4)));
                }
#pragma unroll
            for (int ks = 0; ks < 2; ks++)
#pragma unroll
                for (int mt = 0; mt < 4; mt++)
#pragma unroll
                    for (int nt = 0; nt < 8; nt++)
                        mma8(acc[mt][nt], a[ks][mt], b[nt][ks * 2], b[nt][ks * 2 + 1]);
        }
    }

    // ---------------- epilogue ----------------
    int g = lane >> 2, tig = lane & 3;
#pragma unroll
    for (int mt = 0; mt < 4; mt++) {
#pragma unroll
        for (int half = 0; half < 2; half++) {
            int rl = wm + mt * 16 + g + half * 8;
            if (m0 + rl >= cnt) continue;
            int slot = s_slot[rl];
            if (MODE == 0) {
                float* dst = g_hmid + (size_t)slot * ND;
                const float* bp = bias + (size_t)e * ND;
#pragma unroll
                for (int nt = 0; nt < 8; nt++) {
                    int col = n0 + wn + nt * 8 + 2 * tig;
                    float v0 = acc[mt][nt][half * 2 + 0] + bp[col];
                    float v1 = acc[mt][nt][half * 2 + 1] + bp[col + 1];
                    v0 = 0.5f * v0 * (1.0f + erff(v0 * 0.70710678118654752f));
                    v1 = 0.5f * v1 * (1.0f + erff(v1 * 0.70710678118654752f));
                    *(float2*)(dst + col) = make_float2(tf32r(v0), tf32r(v1));
                }
            } else {
                float wgt = g_slot_w[slot];
                float* dst = Out + (size_t)(slot >> 1) * ND;
                const float* bp = bias + (size_t)e * ND;
#pragma unroll
                for (int nt = 0; nt < 8; nt++) {
                    int col = n0 + wn + nt * 8 + 2 * tig;
                    float v0 = acc[mt][nt][half * 2 + 0] + (split == 0 ? bp[col] : 0.0f);
                    float v1 = acc[mt][nt][half * 2 + 1] + (split == 0 ? bp[col + 1] : 0.0f);
                    atomicAdd(dst + col,     wgt * v0);
                    atomicAdd(dst + col + 1, wgt * v1);
                }
            }
        }
    }
}

// ---------------- launcher ---------------------------------------------------
extern "C" void kernel_launch(void* const* d_in, const int* in_sizes, int n_in,
                              void* d_out, int out_size) {
    const float* x  = (const float*)d_in[0];
    const float* rw = (const float*)d_in[1];
    const float* w1 = (const float*)d_in[2];
    const float* b1 = (const float*)d_in[3];
    const float* w2 = (const float*)d_in[4];
    const float* b2 = (const float*)d_in[5];
    float* out = (float*)d_out;

    void *p_w1c, *p_w2c;
    cudaGetSymbolAddress(&p_w1c, g_w1c);
    cudaGetSymbolAddress(&p_w2c, g_w2c);

    const int SMEM = 4 * 49152 + 128;  // 196736
    cudaFuncSetAttribute(moe_gemm<0, HH, FF, 1>,
                         cudaFuncAttributeMaxDynamicSharedMemorySize, SMEM);
    cudaFuncSetAttribute(moe_gemm<1, FF, HH, 2>,
                         cudaFuncAttributeMaxDynamicSharedMemorySize, SMEM);

    init_kernel<<<(out_size + 255) / 256, 256>>>(out, out_size);
    router_kernel<<<(TT * 32) / 256, 256>>>(x, rw);

    cvt_kernel<<<4736, 256>>>((const float4*)w1, (float4*)p_w1c, EE * FF * HH / 4);
    cvt_kernel<<<4736, 256>>>((const float4*)w2, (float4*)p_w2c, EE * HH * FF / 4);

    // GEMM1: slots x w1^T -> GELU -> hmid (tf32-rounded)
    dim3 g1(FF / 256, (TT + 127) / 128, EE);
    moe_gemm<0, HH, FF, 1><<<g1, 256, SMEM>>>((const float*)p_w1c, b1, out);

    // GEMM2: hmid x w2^T -> weighted scatter-add into out (split-K = 2)
    dim3 g2(HH / 256, (TT + 127) / 128, EE * 2);
    moe_gemm<1, FF, HH, 2><<<g2, 256, SMEM>>>((const float*)p_w2c, b2, out);
}

// round 7
// speedup vs baseline: 1.2293x; 1.2202x over previous
#include <cuda_runtime.h>
#include <math.h>
#include <cstdint>

#define TT 2048      // tokens = B*S
#define EE 8         // experts
#define HH 768       // hidden
#define FF 3072      // ffn hidden

// ---------------- scratch (__device__ globals: allocation-free rule) --------
__device__ float g_hmid[(size_t)TT * 2 * FF];   // 50 MB (tf32-rounded)
__device__ float g_xc [(size_t)TT * HH];        // 6 MB  (tf32-rounded x)
__device__ int   g_cnt[EE];
__device__ int   g_list[EE * TT];
__device__ float g_slot_w[TT * 2];

// ---------------- helpers ----------------------------------------------------
__device__ __forceinline__ uint32_t smem_u32(const void* p) {
    uint32_t a;
    asm("{ .reg .u64 t; cvta.to.shared.u64 t, %1; cvt.u32.u64 %0, t; }" : "=r"(a) : "l"(p));
    return a;
}
__device__ __forceinline__ void cpa16(uint32_t dst, const void* src) {
    asm volatile("cp.async.cg.shared.global [%0], [%1], 16;\n" :: "r"(dst), "l"(src));
}
__device__ __forceinline__ void cpa_commit() { asm volatile("cp.async.commit_group;\n" ::: "memory"); }
__device__ __forceinline__ void cpa_wait1()  { asm volatile("cp.async.wait_group 1;\n" ::: "memory"); }

__device__ __forceinline__ void ldsm4(uint32_t r[4], uint32_t addr) {
    asm volatile("ldmatrix.sync.aligned.m8n8.x4.shared.b16 {%0,%1,%2,%3}, [%4];"
                 : "=r"(r[0]), "=r"(r[1]), "=r"(r[2]), "=r"(r[3]) : "r"(addr));
}
__device__ __forceinline__ float tf32r(float v) {
    uint32_t t;
    asm("cvt.rna.tf32.f32 %0, %1;" : "=r"(t) : "f"(v));
    return __uint_as_float(t);
}
__device__ __forceinline__ void mma8(float c[4], const uint32_t a[4],
                                     uint32_t b0, uint32_t b1) {
    asm volatile(
        "mma.sync.aligned.m16n8k8.row.col.f32.tf32.tf32.f32 "
        "{%0,%1,%2,%3}, {%4,%5,%6,%7}, {%8,%9}, {%0,%1,%2,%3};"
        : "+f"(c[0]), "+f"(c[1]), "+f"(c[2]), "+f"(c[3])
        : "r"(a[0]), "r"(a[1]), "r"(a[2]), "r"(a[3]), "r"(b0), "r"(b1));
}

// ---------------- init / router ----------------------------------------------
__global__ void init_kernel(float* out, int out_size) {
    int i = blockIdx.x * blockDim.x + threadIdx.x;
    if (i < out_size) out[i] = 0.0f;
    if (i < EE) g_cnt[i] = 0;
}

// Router also writes the tf32-rounded copy of x (g_xc).
__global__ void router_kernel(const float* __restrict__ x,
                              const float* __restrict__ rw) {
    int gw   = (blockIdx.x * blockDim.x + threadIdx.x) >> 5;
    int lane = threadIdx.x & 31;
    if (gw >= TT) return;
    const float* xt = x + (size_t)gw * HH;
    float xv[HH / 32];
#pragma unroll
    for (int i = 0; i < HH / 32; i++) xv[i] = xt[lane + 32 * i];
    float* xc = g_xc + (size_t)gw * HH;
#pragma unroll
    for (int i = 0; i < HH / 32; i++) xc[lane + 32 * i] = tf32r(xv[i]);
    float lg[EE];
#pragma unroll
    for (int e = 0; e < EE; e++) {
        const float* w = rw + (size_t)e * HH;
        float s = 0.0f;
#pragma unroll
        for (int i = 0; i < HH / 32; i++) s = fmaf(xv[i], w[lane + 32 * i], s);
#pragma unroll
        for (int o = 16; o; o >>= 1) s += __shfl_xor_sync(0xffffffffu, s, o);
        lg[e] = s;
    }
    if (lane == 0) {
        int i0 = 0;
#pragma unroll
        for (int e = 1; e < EE; e++) if (lg[e] > lg[i0]) i0 = e;
        int i1 = (i0 == 0) ? 1 : 0;
#pragma unroll
        for (int e = 0; e < EE; e++) {
            if (e == i0 || e == i1) continue;
            if (lg[e] > lg[i1]) i1 = e;
        }
        float ex = expf(lg[i1] - lg[i0]);
        float inv = 1.0f / (1.0f + ex);
        g_slot_w[gw * 2]     = inv;
        g_slot_w[gw * 2 + 1] = ex * inv;
        int p = atomicAdd(&g_cnt[i0], 1); g_list[i0 * TT + p] = gw * 2;
        int q = atomicAdd(&g_cnt[i1], 1); g_list[i1 * TT + q] = gw * 2 + 1;
    }
}

// ---------------- mma.sync tf32 grouped GEMM ---------------------------------
// A operands are pre-rounded to tf32 (router / GEMM1 epilogue); W operands are
// raw fp32 (HMMA tf32 truncates to top bits — no cvt anywhere in the loop).
// MODE 0: A = g_xc[token],  W = w1[e] -> bias + GELU -> tf32 -> g_hmid[slot]
// MODE 1: A = g_hmid[slot], W = w2[e] -> weighted atomicAdd into Out (split-K)
template <int MODE, int KD, int ND, int NSPLIT>
__global__ __launch_bounds__(256, 2) void moe_gemm(
    const float* __restrict__ W,
    const float* __restrict__ bias, float* __restrict__ Out) {
    constexpr int BM = 128, BN = 128, BK = 32;
    constexpr int KSP = KD / NSPLIT;
    constexpr int NSLAB = KSP / BK;
    constexpr int STAGE = (BM + BN) * BK * 4;   // 32 KB

    extern __shared__ char dsm[];
    __shared__ int s_slot[BM];

    int e = blockIdx.z / NSPLIT, split = blockIdx.z % NSPLIT;
    int cnt = g_cnt[e];
    int m0 = blockIdx.y * BM;
    if (m0 >= cnt) return;
    int n0 = blockIdx.x * BN;
    int kbase = split * KSP;
    int tid = threadIdx.x, lane = tid & 31, wid = tid >> 5;
    int wm = (wid & 3) * 32, wn = (wid >> 2) * 64;

    const float* __restrict__ Ap = (MODE == 0) ? g_xc : g_hmid;
    const float* __restrict__ Wb = W + (size_t)e * ND * KD;

    for (int i = tid; i < BM; i += 256) {
        int r = m0 + i;
        s_slot[i] = g_list[e * TT + (r < cnt ? r : cnt - 1)];
    }
    __syncthreads();

    uint32_t sb = (smem_u32(dsm) + 127u) & ~127u;

    auto fill = [&](int st, int s) {
        int k0 = kbase + s * BK;
        uint32_t as = sb + st * STAGE;
        uint32_t bs = as + BM * 128;
#pragma unroll
        for (int j = 0; j < 4; j++) {
            int idx = tid + j * 256;
            int r = idx >> 3, c = idx & 7;
            size_t arow = (MODE == 0) ? (size_t)(s_slot[r] >> 1) : (size_t)s_slot[r];
            cpa16(as + r * 128 + ((c * 16) ^ ((r & 7) << 4)),
                  Ap + arow * KD + k0 + c * 4);
        }
#pragma unroll
        for (int j = 0; j < 4; j++) {
            int idx = tid + j * 256;
            int r = idx >> 3, c = idx & 7;
            cpa16(bs + r * 128 + ((c * 16) ^ ((r & 7) << 4)),
                  Wb + (size_t)(n0 + r) * KD + k0 + c * 4);
        }
    };

    fill(0, 0); cpa_commit();
    fill(1, 1); cpa_commit();

    float acc[2][8][4];
#pragma unroll
    for (int mt = 0; mt < 2; mt++)
#pragma unroll
        for (int nt = 0; nt < 8; nt++)
#pragma unroll
            for (int q = 0; q < 4; q++) acc[mt][nt][q] = 0.0f;

    int a_row = lane & 15;            // row within m16 tile
    int a_kx  = (lane >> 4) << 4;     // 0 or 16 bytes
    int b_row = lane & 7;             // row within n8 tile
    int b_kx  = (lane >> 3) << 4;     // 0,16,32,48 bytes

    for (int s = 0; s < NSLAB; s++) {
        cpa_wait1();
        __syncthreads();
        if (s + 2 < NSLAB) fill((s + 2) % 3, s + 2);
        cpa_commit();

        uint32_t ab = sb + (s % 3) * STAGE;
        uint32_t bb = ab + BM * 128;
#pragma unroll
        for (int kh = 0; kh < 2; kh++) {          // 64-byte k-halves of the slab
            uint32_t b[8][4];
#pragma unroll
            for (int nt = 0; nt < 8; nt++) {
                int row = wn + nt * 8 + b_row;
                int kb  = kh * 64 + b_kx;
                ldsm4(b[nt], bb + row * 128 + (kb ^ ((row & 7) << 4)));
            }
#pragma unroll
            for (int ks = 0; ks < 2; ks++) {      // k8 steps within the half
                uint32_t a[2][4];
#pragma unroll
                for (int mt = 0; mt < 2; mt++) {
                    int row = wm + mt * 16 + a_row;
                    int kb  = kh * 64 + ks * 32 + a_kx;
                    ldsm4(a[mt], ab + row * 128 + (kb ^ ((row & 7) << 4)));
                }
#pragma unroll
                for (int mt = 0; mt < 2; mt++)
#pragma unroll
                    for (int nt = 0; nt < 8; nt++)
                        mma8(acc[mt][nt], a[mt], b[nt][ks * 2], b[nt][ks * 2 + 1]);
            }
        }
    }

    // ---------------- epilogue ----------------
    int g = lane >> 2, tig = lane & 3;
#pragma unroll
    for (int mt = 0; mt < 2; mt++) {
#pragma unroll
        for (int half = 0; half < 2; half++) {
            int rl = wm + mt * 16 + g + half * 8;
            if (m0 + rl >= cnt) continue;
            int slot = s_slot[rl];
            if (MODE == 0) {
                float* dst = g_hmid + (size_t)slot * ND;
                const float* bp = bias + (size_t)e * ND;
#pragma unroll
                for (int nt = 0; nt < 8; nt++) {
                    int col = n0 + wn + nt * 8 + 2 * tig;
                    float v0 = acc[mt][nt][half * 2 + 0] + bp[col];
                    float v1 = acc[mt][nt][half * 2 + 1] + bp[col + 1];
                    v0 = 0.5f * v0 * (1.0f + erff(v0 * 0.70710678118654752f));
                    v1 = 0.5f * v1 * (1.0f + erff(v1 * 0.70710678118654752f));
                    *(float2*)(dst + col) = make_float2(tf32r(v0), tf32r(v1));
                }
            } else {
                float wgt = g_slot_w[slot];
                float* dst = Out + (size_t)(slot >> 1) * ND;
                const float* bp = bias + (size_t)e * ND;
#pragma unroll
                for (int nt = 0; nt < 8; nt++) {
                    int col = n0 + wn + nt * 8 + 2 * tig;
                    float v0 = acc[mt][nt][half * 2 + 0] + (split == 0 ? bp[col] : 0.0f);
                    float v1 = acc[mt][nt][half * 2 + 1] + (split == 0 ? bp[col + 1] : 0.0f);
                    atomicAdd(dst + col,     wgt * v0);
                    atomicAdd(dst + col + 1, wgt * v1);
                }
            }
        }
    }
}

// ---------------- launcher ---------------------------------------------------
extern "C" void kernel_launch(void* const* d_in, const int* in_sizes, int n_in,
                              void* d_out, int out_size) {
    const float* x  = (const float*)d_in[0];
    const float* rw = (const float*)d_in[1];
    const float* w1 = (const float*)d_in[2];
    const float* b1 = (const float*)d_in[3];
    const float* w2 = (const float*)d_in[4];
    const float* b2 = (const float*)d_in[5];
    float* out = (float*)d_out;

    const int SMEM = 3 * 32768 + 128;
    cudaFuncSetAttribute(moe_gemm<0, HH, FF, 1>,
                         cudaFuncAttributeMaxDynamicSharedMemorySize, SMEM);
    cudaFuncSetAttribute(moe_gemm<1, FF, HH, 2>,
                         cudaFuncAttributeMaxDynamicSharedMemorySize, SMEM);

    init_kernel<<<(out_size + 255) / 256, 256>>>(out, out_size);
    router_kernel<<<(TT * 32) / 256, 256>>>(x, rw);

    // GEMM1: slots x w1^T (raw fp32, HW-truncated to tf32) -> GELU -> hmid
    dim3 g1(FF / 128, (TT + 127) / 128, EE);
    moe_gemm<0, HH, FF, 1><<<g1, 256, SMEM>>>(w1, b1, out);

    // GEMM2: hmid x w2^T -> weighted scatter-add into out (split-K = 2)
    dim3 g2(HH / 128, (TT + 127) / 128, EE * 2);
    moe_gemm<1, FF, HH, 2><<<g2, 256, SMEM>>>(w2, b2, out);
}

// round 8
// speedup vs baseline: 1.7371x; 1.4131x over previous
#include <cuda_runtime.h>
#include <cuda_fp16.h>
#include <math.h>
#include <cstdint>

#define TT 2048      // tokens = B*S
#define EE 8         // experts
#define HH 768       // hidden
#define FF 3072      // ffn hidden

// ---------------- scratch (__device__ globals: allocation-free rule) --------
__device__ __half g_hmid[(size_t)TT * 2 * FF];  // 25 MB (fp16 mid activations)
__device__ __half g_xh [(size_t)TT * HH];       // 3 MB  (fp16 x)
__device__ __half g_w1h[(size_t)EE * FF * HH];  // 37.7 MB (fp16 w1)
__device__ __half g_w2h[(size_t)EE * HH * FF];  // 37.7 MB (fp16 w2)
__device__ int    g_cnt[EE];
__device__ int    g_list[EE * TT];
__device__ float  g_slot_w[TT * 2];

// ---------------- helpers ----------------------------------------------------
__device__ __forceinline__ uint32_t smem_u32(const void* p) {
    uint32_t a;
    asm("{ .reg .u64 t; cvta.to.shared.u64 t, %1; cvt.u32.u64 %0, t; }" : "=r"(a) : "l"(p));
    return a;
}
__device__ __forceinline__ void cpa16(uint32_t dst, const void* src) {
    asm volatile("cp.async.cg.shared.global [%0], [%1], 16;\n" :: "r"(dst), "l"(src));
}
__device__ __forceinline__ void cpa_commit() { asm volatile("cp.async.commit_group;\n" ::: "memory"); }
__device__ __forceinline__ void cpa_wait1()  { asm volatile("cp.async.wait_group 1;\n" ::: "memory"); }

__device__ __forceinline__ void ldsm4(uint32_t r[4], uint32_t addr) {
    asm volatile("ldmatrix.sync.aligned.m8n8.x4.shared.b16 {%0,%1,%2,%3}, [%4];"
                 : "=r"(r[0]), "=r"(r[1]), "=r"(r[2]), "=r"(r[3]) : "r"(addr));
}
__device__ __forceinline__ void mma16(float c[4], const uint32_t a[4],
                                      uint32_t b0, uint32_t b1) {
    asm volatile(
        "mma.sync.aligned.m16n8k16.row.col.f32.f16.f16.f32 "
        "{%0,%1,%2,%3}, {%4,%5,%6,%7}, {%8,%9}, {%0,%1,%2,%3};"
        : "+f"(c[0]), "+f"(c[1]), "+f"(c[2]), "+f"(c[3])
        : "r"(a[0]), "r"(a[1]), "r"(a[2]), "r"(a[3]), "r"(b0), "r"(b1));
}

// ---------------- init / router / convert ------------------------------------
__global__ void init_kernel(float* out, int out_size) {
    int i = blockIdx.x * blockDim.x + threadIdx.x;
    if (i < out_size) out[i] = 0.0f;
    if (i < EE) g_cnt[i] = 0;
}

// fp32 -> fp16 streaming convert: each thread converts 8 floats per step.
__global__ void cvt_half_kernel(const float4* __restrict__ src,
                                uint4* __restrict__ dst, int n8) {
    int i = blockIdx.x * blockDim.x + threadIdx.x;
    int stride = gridDim.x * blockDim.x;
    for (; i < n8; i += stride) {
        float4 v0 = src[2 * i], v1 = src[2 * i + 1];
        __half2 h0 = __floats2half2_rn(v0.x, v0.y);
        __half2 h1 = __floats2half2_rn(v0.z, v0.w);
        __half2 h2 = __floats2half2_rn(v1.x, v1.y);
        __half2 h3 = __floats2half2_rn(v1.z, v1.w);
        uint4 o;
        o.x = *(uint32_t*)&h0; o.y = *(uint32_t*)&h1;
        o.z = *(uint32_t*)&h2; o.w = *(uint32_t*)&h3;
        dst[i] = o;
    }
}

// Router: logits/top-2/softmax in fp32; also writes fp16 copy of x.
__global__ void router_kernel(const float* __restrict__ x,
                              const float* __restrict__ rw) {
    int gw   = (blockIdx.x * blockDim.x + threadIdx.x) >> 5;
    int lane = threadIdx.x & 31;
    if (gw >= TT) return;
    const float* xt = x + (size_t)gw * HH;
    float xv[HH / 32];
#pragma unroll
    for (int i = 0; i < HH / 32; i++) xv[i] = xt[lane + 32 * i];
    __half* xc = g_xh + (size_t)gw * HH;
#pragma unroll
    for (int i = 0; i < HH / 32; i++) xc[lane + 32 * i] = __float2half_rn(xv[i]);
    float lg[EE];
#pragma unroll
    for (int e = 0; e < EE; e++) {
        const float* w = rw + (size_t)e * HH;
        float s = 0.0f;
#pragma unroll
        for (int i = 0; i < HH / 32; i++) s = fmaf(xv[i], w[lane + 32 * i], s);
#pragma unroll
        for (int o = 16; o; o >>= 1) s += __shfl_xor_sync(0xffffffffu, s, o);
        lg[e] = s;
    }
    if (lane == 0) {
        int i0 = 0;
#pragma unroll
        for (int e = 1; e < EE; e++) if (lg[e] > lg[i0]) i0 = e;
        int i1 = (i0 == 0) ? 1 : 0;
#pragma unroll
        for (int e = 0; e < EE; e++) {
            if (e == i0 || e == i1) continue;
            if (lg[e] > lg[i1]) i1 = e;
        }
        float ex = expf(lg[i1] - lg[i0]);
        float inv = 1.0f / (1.0f + ex);
        g_slot_w[gw * 2]     = inv;
        g_slot_w[gw * 2 + 1] = ex * inv;
        int p = atomicAdd(&g_cnt[i0], 1); g_list[i0 * TT + p] = gw * 2;
        int q = atomicAdd(&g_cnt[i1], 1); g_list[i1 * TT + q] = gw * 2 + 1;
    }
}

// ---------------- mma.sync fp16 grouped GEMM ---------------------------------
// CTA tile 128x128, BK=64 halves (128 B rows), 8 warps (4m x 2n, 32x64 tiles),
// 3-stage cp.async, 2 CTAs/SM. fp32 accumulate.
// MODE 0: A = g_xh[token],  W = g_w1h[e] -> bias + GELU -> fp16 -> g_hmid[slot]
// MODE 1: A = g_hmid[slot], W = g_w2h[e] -> weighted atomicAdd into Out (split-K)
template <int MODE, int KD, int ND, int NSPLIT>
__global__ __launch_bounds__(256, 2) void moe_gemm(
    const __half* __restrict__ W,
    const float* __restrict__ bias, float* __restrict__ Out) {
    constexpr int BM = 128, BN = 128, BK = 64;
    constexpr int KSP = KD / NSPLIT;
    constexpr int NSLAB = KSP / BK;
    constexpr int STAGE = (BM + BN) * 128;      // 32 KB (128 B per row)

    extern __shared__ char dsm[];
    __shared__ int s_slot[BM];

    int e = blockIdx.z / NSPLIT, split = blockIdx.z % NSPLIT;
    int cnt = g_cnt[e];
    int m0 = blockIdx.y * BM;
    if (m0 >= cnt) return;
    int n0 = blockIdx.x * BN;
    int kbase = split * KSP;
    int tid = threadIdx.x, lane = tid & 31, wid = tid >> 5;
    int wm = (wid & 3) * 32, wn = (wid >> 2) * 64;

    const __half* __restrict__ Ap = (MODE == 0) ? g_xh : g_hmid;
    const __half* __restrict__ Wb = W + (size_t)e * ND * KD;

    for (int i = tid; i < BM; i += 256) {
        int r = m0 + i;
        s_slot[i] = g_list[e * TT + (r < cnt ? r : cnt - 1)];
    }
    __syncthreads();

    uint32_t sb = (smem_u32(dsm) + 127u) & ~127u;

    auto fill = [&](int st, int s) {
        int k0 = kbase + s * BK;
        uint32_t as = sb + st * STAGE;
        uint32_t bs = as + BM * 128;
#pragma unroll
        for (int j = 0; j < 4; j++) {            // A: 128 rows x 8 x 16B
            int idx = tid + j * 256;
            int r = idx >> 3, c = idx & 7;
            size_t arow = (MODE == 0) ? (size_t)(s_slot[r] >> 1) : (size_t)s_slot[r];
            cpa16(as + r * 128 + ((c * 16) ^ ((r & 7) << 4)),
                  Ap + arow * KD + k0 + c * 8);
        }
#pragma unroll
        for (int j = 0; j < 4; j++) {            // B: 128 rows x 8 x 16B
            int idx = tid + j * 256;
            int r = idx >> 3, c = idx & 7;
            cpa16(bs + r * 128 + ((c * 16) ^ ((r & 7) << 4)),
                  Wb + (size_t)(n0 + r) * KD + k0 + c * 8);
        }
    };

    fill(0, 0); cpa_commit();
    fill(1, 1); cpa_commit();

    float acc[2][8][4];
#pragma unroll
    for (int mt = 0; mt < 2; mt++)
#pragma unroll
        for (int nt = 0; nt < 8; nt++)
#pragma unroll
            for (int q = 0; q < 4; q++) acc[mt][nt][q] = 0.0f;

    int a_row = lane & 15;            // row within m16 tile
    int a_kx  = (lane >> 4) << 4;     // 0 or 16 bytes (k8 halves)
    int b_row = lane & 7;             // row within n8 tile
    int b_kx  = (lane >> 3) << 4;     // 0,16,32,48 bytes (4 k8 tiles)

    for (int s = 0; s < NSLAB; s++) {
        cpa_wait1();
        __syncthreads();
        if (s + 2 < NSLAB) fill((s + 2) % 3, s + 2);
        cpa_commit();

        uint32_t ab = sb + (s % 3) * STAGE;
        uint32_t bb = ab + BM * 128;
#pragma unroll
        for (int kh = 0; kh < 2; kh++) {          // k32-halves of the slab
            uint32_t b[8][4];
#pragma unroll
            for (int nt = 0; nt < 8; nt++) {
                int row = wn + nt * 8 + b_row;
                int kb  = kh * 64 + b_kx;
                ldsm4(b[nt], bb + row * 128 + (kb ^ ((row & 7) << 4)));
            }
#pragma unroll
            for (int ks = 0; ks < 2; ks++) {      // k16 steps within the half
                uint32_t a[2][4];
#pragma unroll
                for (int mt = 0; mt < 2; mt++) {
                    int row = wm + mt * 16 + a_row;
                    int kb  = kh * 64 + ks * 32 + a_kx;
                    ldsm4(a[mt], ab + row * 128 + (kb ^ ((row & 7) << 4)));
                }
#pragma unroll
                for (int mt = 0; mt < 2; mt++)
#pragma unroll
                    for (int nt = 0; nt < 8; nt++)
                        mma16(acc[mt][nt], a[mt], b[nt][ks * 2], b[nt][ks * 2 + 1]);
            }
        }
    }

    // ---------------- epilogue ----------------
    int g = lane >> 2, tig = lane & 3;
#pragma unroll
    for (int mt = 0; mt < 2; mt++) {
#pragma unroll
        for (int half = 0; half < 2; half++) {
            int rl = wm + mt * 16 + g + half * 8;
            if (m0 + rl >= cnt) continue;
            int slot = s_slot[rl];
            if (MODE == 0) {
                __half* dst = g_hmid + (size_t)slot * ND;
                const float* bp = bias + (size_t)e * ND;
#pragma unroll
                for (int nt = 0; nt < 8; nt++) {
                    int col = n0 + wn + nt * 8 + 2 * tig;
                    float v0 = acc[mt][nt][half * 2 + 0] + bp[col];
                    float v1 = acc[mt][nt][half * 2 + 1] + bp[col + 1];
                    v0 = 0.5f * v0 * (1.0f + erff(v0 * 0.70710678118654752f));
                    v1 = 0.5f * v1 * (1.0f + erff(v1 * 0.70710678118654752f));
                    *(__half2*)(dst + col) = __floats2half2_rn(v0, v1);
                }
            } else {
                float wgt = g_slot_w[slot];
                float* dst = Out + (size_t)(slot >> 1) * ND;
                const float* bp = bias + (size_t)e * ND;
#pragma unroll
                for (int nt = 0; nt < 8; nt++) {
                    int col = n0 + wn + nt * 8 + 2 * tig;
                    float v0 = acc[mt][nt][half * 2 + 0] + (split == 0 ? bp[col] : 0.0f);
                    float v1 = acc[mt][nt][half * 2 + 1] + (split == 0 ? bp[col + 1] : 0.0f);
                    atomicAdd(dst + col,     wgt * v0);
                    atomicAdd(dst + col + 1, wgt * v1);
                }
            }
        }
    }
}

// ---------------- launcher ---------------------------------------------------
extern "C" void kernel_launch(void* const* d_in, const int* in_sizes, int n_in,
                              void* d_out, int out_size) {
    const float* x  = (const float*)d_in[0];
    const float* rw = (const float*)d_in[1];
    const float* w1 = (const float*)d_in[2];
    const float* b1 = (const float*)d_in[3];
    const float* w2 = (const float*)d_in[4];
    const float* b2 = (const float*)d_in[5];
    float* out = (float*)d_out;

    void *p_w1h, *p_w2h;
    cudaGetSymbolAddress(&p_w1h, g_w1h);
    cudaGetSymbolAddress(&p_w2h, g_w2h);

    const int SMEM = 3 * 32768 + 128;
    cudaFuncSetAttribute(moe_gemm<0, HH, FF, 1>,
                         cudaFuncAttributeMaxDynamicSharedMemorySize, SMEM);
    cudaFuncSetAttribute(moe_gemm<1, FF, HH, 2>,
                         cudaFuncAttributeMaxDynamicSharedMemorySize, SMEM);

    init_kernel<<<(out_size + 255) / 256, 256>>>(out, out_size);
    router_kernel<<<(TT * 32) / 256, 256>>>(x, rw);

    cvt_half_kernel<<<4736, 256>>>((const float4*)w1, (uint4*)p_w1h, EE * FF * HH / 8);
    cvt_half_kernel<<<4736, 256>>>((const float4*)w2, (uint4*)p_w2h, EE * HH * FF / 8);

    // GEMM1: slots x w1^T (fp16) -> GELU -> hmid (fp16)
    dim3 g1(FF / 128, (TT + 127) / 128, EE);
    moe_gemm<0, HH, FF, 1><<<g1, 256, SMEM>>>((const __half*)p_w1h, b1, out);

    // GEMM2: hmid x w2^T (fp16) -> weighted scatter-add into out (split-K = 2)
    dim3 g2(HH / 128, (TT + 127) / 128, EE * 2);
    moe_gemm<1, FF, HH, 2><<<g2, 256, SMEM>>>((const __half*)p_w2h, b2, out);
}